// round 2
// baseline (speedup 1.0000x reference)
#include <cuda_runtime.h>
#include <cstdint>

// Problem constants
#define NROWS   24000          // BS*Q
#define NTGT    2400           // BS*NT
#define KCLS    256
#define R_TILE  32             // rows per block in main kernel
#define TPT     4              // targets per thread
#define BLOCK   256
#define TT      (BLOCK*TPT)    // 1024 targets per block-group
#define NGROUPS 3              // ceil(2400/1024)

// Scratch (allocation-free: __device__ globals)
__device__ float  g_diff[NROWS * KCLS];     // focal class cost diff + 2.0
__device__ float4 g_rowrec[NROWS * 3];      // {cx,cy,w,h},{x1,y1,x2,y2},{area,-,-,-}
__device__ float4 g_trec[NTGT * 3];

// ---------------------------------------------------------------------------
// Kernel 1: per-(n,k) focal classification cost diff' = pos - neg + 2
// ---------------------------------------------------------------------------
__global__ void k_diff(const float* __restrict__ logits) {
    int i = blockIdx.x * blockDim.x + threadIdx.x;
    if (i >= NROWS * KCLS) return;
    float x = logits[i];
    float e = __expf(-x);
    float p = __fdividef(1.0f, 1.0f + e);   // sigmoid
    float omp = 1.0f - p;
    // neg = (1-alpha) * p^2 * -log(1-p+eps);  pos = alpha * (1-p)^2 * -log(p+eps)
    float neg = 0.75f * p * p   * (-__logf(omp + 1e-8f));
    float pos = 0.25f * omp*omp * (-__logf(p   + 1e-8f));
    g_diff[i] = pos - neg + 2.0f;           // fold GIoU's "+2" constant in here
}

// ---------------------------------------------------------------------------
// Kernel 2: box records (cxcywh, xyxy, area) for rows and targets
// ---------------------------------------------------------------------------
__global__ void k_rec(const float* __restrict__ boxes, float4* __restrict__ rec, int n) {
    int i = blockIdx.x * blockDim.x + threadIdx.x;
    if (i >= n) return;
    float4 b = ((const float4*)boxes)[i];   // cx, cy, w, h
    float hw = 0.5f * b.z, hh = 0.5f * b.w;
    rec[i*3 + 0] = b;
    rec[i*3 + 1] = make_float4(b.x - hw, b.y - hh, b.x + hw, b.y + hh);
    rec[i*3 + 2] = make_float4(b.z * b.w, 0.f, 0.f, 0.f);
}

// ---------------------------------------------------------------------------
// Kernel 3: main pair kernel. Block = 32 rows x 1024 targets.
// ---------------------------------------------------------------------------
__global__ __launch_bounds__(BLOCK) void k_main(const int* __restrict__ tids,
                                                float* __restrict__ out) {
    __shared__ float4 srow[R_TILE * 3];
    __shared__ float  sdiff[R_TILE * KCLS];   // 32 KB

    const int tid = threadIdx.x;
    const int r0  = blockIdx.x * R_TILE;
    const int t0  = blockIdx.y * TT + tid * TPT;
    const bool valid = (t0 < NTGT);

    // Stage row records
    for (int i = tid; i < R_TILE * 3; i += BLOCK)
        srow[i] = g_rowrec[r0 * 3 + i];
    // Stage diff rows (32 x 256 floats = 8192 float4 / 256 threads... = 8 each)
    {
        const float4* gd  = (const float4*)(g_diff + (size_t)r0 * KCLS);
        float4*       sd4 = (float4*)sdiff;
        #pragma unroll
        for (int i = 0; i < (R_TILE * KCLS / 4) / BLOCK; i++)
            sd4[tid + i * BLOCK] = gd[tid + i * BLOCK];
    }

    // Target data -> registers (constant across row loop)
    float tcx[TPT], tcy[TPT], tw[TPT], th[TPT];
    float tx1[TPT], ty1[TPT], tx2[TPT], ty2[TPT], tarea[TPT];
    int   id[TPT];
    if (valid) {
        #pragma unroll
        for (int j = 0; j < TPT; j++) {
            float4 a = g_trec[(t0 + j) * 3 + 0];
            float4 b = g_trec[(t0 + j) * 3 + 1];
            float4 c = g_trec[(t0 + j) * 3 + 2];
            tcx[j] = a.x; tcy[j] = a.y; tw[j] = a.z; th[j] = a.w;
            tx1[j] = b.x; ty1[j] = b.y; tx2[j] = b.z; ty2[j] = b.w;
            tarea[j] = c.x;
        }
        int4 iv = *(const int4*)(tids + t0);
        id[0] = iv.x; id[1] = iv.y; id[2] = iv.z; id[3] = iv.w;
    }
    __syncthreads();

    float* op = out + (size_t)r0 * NTGT + t0;

    #pragma unroll 1
    for (int r = 0; r < R_TILE; r++) {
        float4 ra = srow[r * 3 + 0];   // cx cy w h
        float4 rb = srow[r * 3 + 1];   // x1 y1 x2 y2
        float  rarea = srow[r * 3 + 2].x;
        if (valid) {
            float res[TPT];
            #pragma unroll
            for (int j = 0; j < TPT; j++) {
                float d = sdiff[r * KCLS + id[j]];            // class cost (+2)
                // L1 on cxcywh
                float bb = fabsf(ra.x - tcx[j]) + fabsf(ra.y - tcy[j])
                         + fabsf(ra.z - tw[j])  + fabsf(ra.w - th[j]);
                // intersection
                float lx = fmaxf(rb.x, tx1[j]), ly = fmaxf(rb.y, ty1[j]);
                float hx = fminf(rb.z, tx2[j]), hy = fminf(rb.w, ty2[j]);
                float iw = fmaxf(hx - lx, 0.0f), ih = fmaxf(hy - ly, 0.0f);
                float inter = iw * ih;
                float uni   = rarea + tarea[j] - inter;
                // enclosing box (always non-negative extents)
                float ex1 = fminf(rb.x, tx1[j]), ey1 = fminf(rb.y, ty1[j]);
                float ex2 = fmaxf(rb.z, tx2[j]), ey2 = fmaxf(rb.w, ty2[j]);
                float ea  = (ex2 - ex1) * (ey2 - ey1);
                float ru, re;
                asm("rcp.approx.f32 %0, %1;" : "=f"(ru) : "f"(uni));
                asm("rcp.approx.f32 %0, %1;" : "=f"(re) : "f"(ea));
                // C = 5*bbox + (class + 2) - 2*inter/uni - 2*uni/ea
                float c = __fmaf_rn(5.0f, bb, d);
                c = __fmaf_rn(-2.0f * inter, ru, c);
                c = __fmaf_rn(-2.0f * uni,   re, c);
                res[j] = c;
            }
            *(float4*)op = make_float4(res[0], res[1], res[2], res[3]);
        }
        op += NTGT;
    }
}

// ---------------------------------------------------------------------------
extern "C" void kernel_launch(void* const* d_in, const int* in_sizes, int n_in,
                              void* d_out, int out_size) {
    const float* logits = (const float*)d_in[0];   // [16,1500,256]
    const float* pboxes = (const float*)d_in[1];   // [24000,4]
    const float* tboxes = (const float*)d_in[2];   // [2400,4]
    const int*   tids   = (const int*)  d_in[3];   // [2400]
    float* out = (float*)d_out;

    // Resolve device-symbol addresses for the record kernels
    // (g_rowrec / g_trec are written via pointer args)
    static float4* rowrec_ptr = nullptr;
    static float4* trec_ptr   = nullptr;
    if (!rowrec_ptr) {
        cudaGetSymbolAddress((void**)&rowrec_ptr, g_rowrec);
        cudaGetSymbolAddress((void**)&trec_ptr,   g_trec);
    }

    k_diff<<<(NROWS * KCLS + 255) / 256, 256>>>(logits);
    k_rec<<<(NROWS + 255) / 256, 256>>>(pboxes, rowrec_ptr, NROWS);
    k_rec<<<(NTGT + 255) / 256, 256>>>(tboxes, trec_ptr, NTGT);

    dim3 grid(NROWS / R_TILE, NGROUPS);
    k_main<<<grid, BLOCK>>>(tids, out);
}

// round 3
// speedup vs baseline: 1.0957x; 1.0957x over previous
#include <cuda_runtime.h>
#include <cstdint>

// Problem constants
#define NROWS   24000          // BS*Q
#define NTGT    2400           // BS*NT
#define KCLS    256
#define R_TILE  32             // rows per block in main kernel
#define TPT     5              // targets per thread (strided by BLOCK)
#define BLOCK   160            // 5 warps
#define TT      (BLOCK*TPT)    // 800 targets per block-group
#define NGROUPS 3              // 3 * 800 = 2400 exactly -> zero lane waste

// Scratch (allocation-free: __device__ globals)
__device__ float  g_diff[NROWS * KCLS];     // focal class cost diff + 2.0
__device__ float4 g_rowrec[NROWS * 3];      // {cx,cy,w,h},{x1,y1,x2,y2},{area,-,-,-}
__device__ float4 g_trec[NTGT * 3];

// ---------------------------------------------------------------------------
// Kernel 1: per-(n,k) focal classification cost diff' = pos - neg + 2
// ---------------------------------------------------------------------------
__global__ void k_diff(const float* __restrict__ logits) {
    int i = blockIdx.x * blockDim.x + threadIdx.x;
    if (i >= NROWS * KCLS) return;
    float x = logits[i];
    float e = __expf(-x);
    float p = __fdividef(1.0f, 1.0f + e);   // sigmoid
    float omp = 1.0f - p;
    // neg = (1-alpha) * p^2 * -log(1-p+eps);  pos = alpha * (1-p)^2 * -log(p+eps)
    float neg = 0.75f * p * p   * (-__logf(omp + 1e-8f));
    float pos = 0.25f * omp*omp * (-__logf(p   + 1e-8f));
    g_diff[i] = pos - neg + 2.0f;           // fold GIoU's "+2" constant in here
}

// ---------------------------------------------------------------------------
// Kernel 2: box records (cxcywh, xyxy, area) for rows AND targets in one launch
// ---------------------------------------------------------------------------
__global__ void k_rec2(const float* __restrict__ pboxes,
                       const float* __restrict__ tboxes,
                       float4* __restrict__ rowrec,
                       float4* __restrict__ trec) {
    int i = blockIdx.x * blockDim.x + threadIdx.x;
    const float4* src;
    float4* dst;
    int idx;
    if (i < NROWS)            { src = (const float4*)pboxes; dst = rowrec; idx = i; }
    else if (i < NROWS + NTGT){ src = (const float4*)tboxes; dst = trec;   idx = i - NROWS; }
    else return;
    float4 b = src[idx];                    // cx, cy, w, h
    float hw = 0.5f * b.z, hh = 0.5f * b.w;
    dst[idx*3 + 0] = b;
    dst[idx*3 + 1] = make_float4(b.x - hw, b.y - hh, b.x + hw, b.y + hh);
    dst[idx*3 + 2] = make_float4(b.z * b.w, 0.f, 0.f, 0.f);
}

// ---------------------------------------------------------------------------
// Kernel 3: main pair kernel. Block = 32 rows x 800 targets (strided TPT=5).
// ---------------------------------------------------------------------------
__global__ __launch_bounds__(BLOCK, 4) void k_main(const int* __restrict__ tids,
                                                   float* __restrict__ out) {
    __shared__ float4 srow[R_TILE * 3];
    __shared__ float  sdiff[R_TILE * KCLS];   // 32 KB

    const int tid   = threadIdx.x;
    const int r0    = blockIdx.x * R_TILE;
    const int tbase = blockIdx.y * TT + tid;   // thread's first target; stride BLOCK

    // Stage row records (96 float4)
    for (int i = tid; i < R_TILE * 3; i += BLOCK)
        srow[i] = g_rowrec[r0 * 3 + i];
    // Stage diff rows: 32*256 floats = 2048 float4
    {
        const float4* gd  = (const float4*)(g_diff + (size_t)r0 * KCLS);
        float4*       sd4 = (float4*)sdiff;
        for (int i = tid; i < (R_TILE * KCLS) / 4; i += BLOCK)
            sd4[i] = gd[i];
    }

    // Target data -> registers (constant across row loop). All slots valid.
    float tcx[TPT], tcy[TPT], tw[TPT], th[TPT];
    float tx1[TPT], ty1[TPT], tx2[TPT], ty2[TPT], tarea[TPT];
    int   cof[TPT];   // class column (in floats)
    #pragma unroll
    for (int j = 0; j < TPT; j++) {
        int t = tbase + j * BLOCK;
        float4 a = g_trec[t * 3 + 0];
        float4 b = g_trec[t * 3 + 1];
        float4 c = g_trec[t * 3 + 2];
        tcx[j] = a.x; tcy[j] = a.y; tw[j] = a.z; th[j] = a.w;
        tx1[j] = b.x; ty1[j] = b.y; tx2[j] = b.z; ty2[j] = b.w;
        tarea[j] = c.x;
        cof[j] = tids[t];
    }
    __syncthreads();

    float* op = out + (size_t)r0 * NTGT + tbase;

    #pragma unroll 1
    for (int r = 0; r < R_TILE; r++) {
        const float4 ra = srow[r * 3 + 0];   // cx cy w h
        const float4 rb = srow[r * 3 + 1];   // x1 y1 x2 y2
        const float  rarea = srow[r * 3 + 2].x;
        const float* drow = sdiff + r * KCLS;
        #pragma unroll
        for (int j = 0; j < TPT; j++) {
            float d = drow[cof[j]];                       // class cost (+2)
            // L1 on cxcywh
            float bb = fabsf(ra.x - tcx[j]) + fabsf(ra.y - tcy[j])
                     + fabsf(ra.z - tw[j])  + fabsf(ra.w - th[j]);
            // intersection corners
            float lx = fmaxf(rb.x, tx1[j]), ly = fmaxf(rb.y, ty1[j]);
            float hx = fminf(rb.z, tx2[j]), hy = fminf(rb.w, ty2[j]);
            float iwr = hx - lx, ihr = hy - ly;           // unclamped extents
            float iw = fmaxf(iwr, 0.0f), ih = fmaxf(ihr, 0.0f);
            float inter = iw * ih;
            float uni   = (rarea + tarea[j]) - inter;
            // enclosing box via min+max=sum identity:
            //   ew = max(x2) - min(x1) = (rw + tw) - (hx - lx)
            float ew = (ra.z + tw[j]) - iwr;
            float eh = (ra.w + th[j]) - ihr;
            float ea = ew * eh;
            float ru, re;
            asm("rcp.approx.f32 %0, %1;" : "=f"(ru) : "f"(0.5f * uni));
            asm("rcp.approx.f32 %0, %1;" : "=f"(re) : "f"(0.5f * ea));
            // C = 5*bbox + (class + 2) - inter/(0.5*uni) - uni/(0.5*ea)
            float c = __fmaf_rn(5.0f, bb, d);
            c = __fmaf_rn(-inter, ru, c);
            c = __fmaf_rn(-uni,   re, c);
            op[j * BLOCK] = c;
        }
        op += NTGT;
    }
}

// ---------------------------------------------------------------------------
extern "C" void kernel_launch(void* const* d_in, const int* in_sizes, int n_in,
                              void* d_out, int out_size) {
    const float* logits = (const float*)d_in[0];   // [16,1500,256]
    const float* pboxes = (const float*)d_in[1];   // [24000,4]
    const float* tboxes = (const float*)d_in[2];   // [2400,4]
    const int*   tids   = (const int*)  d_in[3];   // [2400]
    float* out = (float*)d_out;

    static float4* rowrec_ptr = nullptr;
    static float4* trec_ptr   = nullptr;
    if (!rowrec_ptr) {
        cudaGetSymbolAddress((void**)&rowrec_ptr, g_rowrec);
        cudaGetSymbolAddress((void**)&trec_ptr,   g_trec);
    }

    k_diff<<<(NROWS * KCLS + 255) / 256, 256>>>(logits);
    k_rec2<<<(NROWS + NTGT + 255) / 256, 256>>>(pboxes, tboxes, rowrec_ptr, trec_ptr);

    dim3 grid(NROWS / R_TILE, NGROUPS);
    k_main<<<grid, BLOCK>>>(tids, out);
}

// round 5
// speedup vs baseline: 1.3009x; 1.1872x over previous
#include <cuda_runtime.h>
#include <cstdint>

// Problem constants
#define NROWS   24000          // BS*Q
#define NTGT    2400           // BS*NT
#define KCLS    256
#define R_TILE  32             // rows per block in main kernel
#define TPT     5              // targets per thread (strided by BLOCK)
#define BLOCK   160            // 5 warps
#define TT      (BLOCK*TPT)    // 800 targets per block-group
#define NGROUPS 3              // 3 * 800 = 2400 exactly -> zero lane waste

// Scratch (allocation-free: __device__ global)
__device__ float g_diff[NROWS * KCLS];     // focal class cost diff + 2.0

// ---------------------------------------------------------------------------
// Kernel 1: per-(n,k) focal classification cost diff' = pos - neg + 2
//   Uses ln(p) = -ln(1+e^{-x}), ln(1-p) = -x - ln(1+e^{-x})  (3 MUFU not 4)
//   float4 vectorized: each thread does 4 elements.
// ---------------------------------------------------------------------------
__global__ void k_diff(const float* __restrict__ logits) {
    int i = blockIdx.x * blockDim.x + threadIdx.x;   // i indexes float4
    float4 x4 = ((const float4*)logits)[i];
    float r[4];
    float xs[4] = {x4.x, x4.y, x4.z, x4.w};
    #pragma unroll
    for (int k = 0; k < 4; k++) {
        float x = xs[k];
        float e = __expf(-x);
        float a = 1.0f + e;
        float s = __logf(a);          // = -ln(p) = softplus(-x)
        float p;
        asm("rcp.approx.f32 %0, %1;" : "=f"(p) : "f"(a));   // sigmoid
        float omp = 1.0f - p;
        // pos = 0.25*(1-p)^2 * (-ln p) = 0.25*omp^2*s
        // neg = 0.75*p^2 * (-ln(1-p)) = 0.75*p^2*(x+s)
        float pos = (omp * omp) * (0.25f * s);
        float neg = (p * p) * (0.75f * (x + s));
        r[k] = (pos - neg) + 2.0f;    // fold GIoU's "+2" constant in
    }
    ((float4*)g_diff)[i] = make_float4(r[0], r[1], r[2], r[3]);
}

// ---------------------------------------------------------------------------
// Kernel 2: main pair kernel. Block = 32 rows x 800 targets (strided TPT=5).
// Correct symmetric-interval identity with HALF-widths (w2 = 0.5*w):
//   mx      = max(|rcx-tcx|, |rw2-tw2|)
//   inter_w = (rw2+tw2) - mx   (clamped >= 0)
//   encl_w  = (rw2+tw2) + mx
// |rw2-tw2| doubles as the L1 width term (x2); |dx| is the L1 center term.
// ---------------------------------------------------------------------------
__global__ __launch_bounds__(BLOCK) void k_main(const float* __restrict__ pboxes,
                                                const float* __restrict__ tboxes,
                                                const int* __restrict__ tids,
                                                float* __restrict__ out) {
    __shared__ float4 sbox[R_TILE];           // {cx, cy, 0.5w, 0.5h}
    __shared__ float  sarea[R_TILE];
    __shared__ float  sdiff[R_TILE * KCLS];   // 32 KB

    const int tid   = threadIdx.x;
    const int r0    = blockIdx.x * R_TILE;
    const int tbase = blockIdx.y * TT + tid;   // thread's first target; stride BLOCK

    // Stage row boxes (half-extents) + areas
    if (tid < R_TILE) {
        float4 b = ((const float4*)pboxes)[r0 + tid];
        sarea[tid] = b.z * b.w;
        sbox[tid]  = make_float4(b.x, b.y, 0.5f * b.z, 0.5f * b.w);
    }
    // Stage diff rows: 32*256 floats = 2048 float4
    {
        const float4* gd  = (const float4*)(g_diff + (size_t)r0 * KCLS);
        float4*       sd4 = (float4*)sdiff;
        for (int i = tid; i < (R_TILE * KCLS) / 4; i += BLOCK)
            sd4[i] = gd[i];
    }

    // Target data -> registers (constant across row loop). All slots valid.
    float tcx[TPT], tcy[TPT], tw2[TPT], th2[TPT], tarea[TPT];
    int   cof[TPT];
    #pragma unroll
    for (int j = 0; j < TPT; j++) {
        int t = tbase + j * BLOCK;
        float4 b = ((const float4*)tboxes)[t];
        tcx[j] = b.x; tcy[j] = b.y;
        tw2[j] = 0.5f * b.z; th2[j] = 0.5f * b.w;
        tarea[j] = b.z * b.w;
        cof[j] = tids[t];
    }
    __syncthreads();

    float* op = out + (size_t)r0 * NTGT + tbase;

    #pragma unroll 1
    for (int r = 0; r < R_TILE; r++) {
        const float4 ra = sbox[r];        // cx cy w2 h2
        const float  rarea = sarea[r];
        const float* drow = sdiff + r * KCLS;
        #pragma unroll
        for (int j = 0; j < TPT; j++) {
            float d = drow[cof[j]];                        // class cost (+2)
            float adx  = fabsf(ra.x - tcx[j]);
            float ady  = fabsf(ra.y - tcy[j]);
            float adwh = fabsf(ra.z - tw2[j]);             // = 0.5*|dw|
            float adhh = fabsf(ra.w - th2[j]);             // = 0.5*|dh|
            // L1 on cxcywh: |dx|+|dy| + 2*(|dw|/2 + |dh|/2)
            float bb = __fmaf_rn(2.0f, adwh + adhh, adx + ady);
            // half-extent sums and the max terms
            float sw2 = ra.z + tw2[j];
            float sh2 = ra.w + th2[j];
            float mxx = fmaxf(adx, adwh);
            float mxy = fmaxf(ady, adhh);
            // intersection / enclosing extents (correct identity)
            float iw = fmaxf(sw2 - mxx, 0.0f);
            float ih = fmaxf(sh2 - mxy, 0.0f);
            float ew = sw2 + mxx;
            float eh = sh2 + mxy;
            float inter = iw * ih;
            float uni   = (rarea + tarea[j]) - inter;
            float ea    = ew * eh;
            float ru, re;
            asm("rcp.approx.f32 %0, %1;" : "=f"(ru) : "f"(uni));
            asm("rcp.approx.f32 %0, %1;" : "=f"(re) : "f"(ea));
            // C = 5*bb + (class+2) - 2*(inter/uni + uni/ea)
            float t1 = uni * re;
            t1 = __fmaf_rn(inter, ru, t1);
            float c = __fmaf_rn(5.0f, bb, d);
            c = __fmaf_rn(-2.0f, t1, c);
            op[j * BLOCK] = c;
        }
        op += NTGT;
    }
}

// ---------------------------------------------------------------------------
extern "C" void kernel_launch(void* const* d_in, const int* in_sizes, int n_in,
                              void* d_out, int out_size) {
    const float* logits = (const float*)d_in[0];   // [16,1500,256]
    const float* pboxes = (const float*)d_in[1];   // [24000,4]
    const float* tboxes = (const float*)d_in[2];   // [2400,4]
    const int*   tids   = (const int*)  d_in[3];   // [2400]
    float* out = (float*)d_out;

    // 6,144,000 elements / 4 per thread / 256 per block = 6000 blocks
    k_diff<<<(NROWS * KCLS) / 4 / 256, 256>>>(logits);

    dim3 grid(NROWS / R_TILE, NGROUPS);
    k_main<<<grid, BLOCK>>>(pboxes, tboxes, tids, out);
}